// round 11
// baseline (speedup 1.0000x reference)
#include <cuda_runtime.h>
#include <cstdint>

// points (B=4, C=84, H=512, W=512) fp32.
// probs = max over channels [0,80); 3x3 NMS (strict > for raster-earlier
// neighbors, >= for later, zero padding); out = points * mask.
//
// Per-batch pipeline for L2 residency (one batch = 84 MB < 126 MB L2):
//   k_probs_part(b): 4 channel-chunks x 20 ch -> 4 partial-max planes,
//                    1024-block grid (saturates HBM), .ca loads warm L2.
//   k_combine(b):    fold 4 partials -> final probs plane (L2).
//   k_mask(b):       3x3 NMS predicate (L2).
//   k_mul(b):        out = points*mask. Reads hit L2 (__ldcs: evict-first,
//                    data dead after). Stores are WRITE-THROUGH (__stwt) so
//                    output lines don't allocate in L2 and evict the
//                    not-yet-read point channels. 4 channels per thread for
//                    MLP=4 and 4x mask-load reuse.
#define B_      4
#define C_      84
#define CP_     80
#define NCHUNK  4
#define CPC     (CP_ / NCHUNK)   // 20
#define H_      512
#define W_      512
#define HW_     (H_ * W_)        // 262144
#define HW4_    (HW_ / 4)        // 65536
#define CGRP    (C_ / 4)         // 21 channel-groups in k_mul

// Scratch (allocation-guard-safe __device__ globals).
__device__ static float g_part [NCHUNK * HW_];  // 4 MB
__device__ static float g_probs[HW_];           // 1 MB
__device__ static float g_mask [HW_];           // 1 MB

// ---------------------------------------------------------------------------
// Kernel 1 (per batch): partial channel max. grid = 1024 blocks.
// ---------------------------------------------------------------------------
__global__ __launch_bounds__(256)
void k_probs_part(const float* __restrict__ pts_b, float* __restrict__ part) {
    int t     = blockIdx.x * blockDim.x + threadIdx.x;  // 0 .. NCHUNK*HW4_-1
    int chunk = t >> 16;                                // HW4_ = 2^16
    int pix4  = t & (HW4_ - 1);
    const float4* src = reinterpret_cast<const float4*>(pts_b)
                        + chunk * CPC * HW4_ + pix4;
    float4 m = src[0];
    #pragma unroll
    for (int c = 1; c < CPC; ++c) {
        float4 v = src[c * HW4_];
        m.x = fmaxf(m.x, v.x);
        m.y = fmaxf(m.y, v.y);
        m.z = fmaxf(m.z, v.z);
        m.w = fmaxf(m.w, v.w);
    }
    reinterpret_cast<float4*>(part)[t] = m;
}

// ---------------------------------------------------------------------------
// Kernel 2 (per batch): combine 4 partial planes -> final probs. All L2.
// ---------------------------------------------------------------------------
__global__ __launch_bounds__(256)
void k_combine(const float* __restrict__ part, float* __restrict__ probs) {
    int t = blockIdx.x * blockDim.x + threadIdx.x;      // 0 .. HW4_-1
    const float4* p = reinterpret_cast<const float4*>(part);
    float4 a = p[t];
    #pragma unroll
    for (int k = 1; k < NCHUNK; ++k) {
        float4 v = p[k * HW4_ + t];
        a.x = fmaxf(a.x, v.x);
        a.y = fmaxf(a.y, v.y);
        a.z = fmaxf(a.z, v.z);
        a.w = fmaxf(a.w, v.w);
    }
    reinterpret_cast<float4*>(probs)[t] = a;
}

// ---------------------------------------------------------------------------
// Kernel 3 (per batch): 3x3 NMS mask. All reads L2/L1 resident.
// ---------------------------------------------------------------------------
__device__ __forceinline__ float nbp(const float* __restrict__ p, int h, int w) {
    if (h < 0 || h >= H_ || w < 0 || w >= W_) return 0.0f;
    return p[(h << 9) + w];
}

__global__ __launch_bounds__(256)
void k_mask(const float* __restrict__ probs, float* __restrict__ mask) {
    int idx = blockIdx.x * blockDim.x + threadIdx.x;    // 0 .. HW_-1
    int h = idx >> 9;
    int w = idx & (W_ - 1);
    float p = probs[idx];
    bool ok =
        (p >  nbp(probs, h - 1, w - 1)) &&
        (p >  nbp(probs, h - 1, w    )) &&
        (p >  nbp(probs, h - 1, w + 1)) &&
        (p >  nbp(probs, h,     w - 1)) &&
        (p >= nbp(probs, h,     w + 1)) &&
        (p >= nbp(probs, h + 1, w - 1)) &&
        (p >= nbp(probs, h + 1, w    )) &&
        (p >= nbp(probs, h + 1, w + 1));
    mask[idx] = ok ? 1.0f : 0.0f;
}

// ---------------------------------------------------------------------------
// Kernel 4 (per batch): out = points * mask.
// Thread (grp, pix4) handles channels grp, grp+21, grp+42, grp+63 at pix4:
// 1 mask load reused 4x, 4 independent load/store pairs (MLP=4).
// ---------------------------------------------------------------------------
__global__ __launch_bounds__(256)
void k_mul(const float* __restrict__ pts_b, const float* __restrict__ mask,
           float* __restrict__ out_b) {
    unsigned g    = blockIdx.x * blockDim.x + threadIdx.x; // < CGRP*HW4_
    unsigned pix4 = g & (HW4_ - 1);
    unsigned grp  = g >> 16;                                // 0 .. 20
    float4 m = reinterpret_cast<const float4*>(mask)[pix4];

    const float4* src = reinterpret_cast<const float4*>(pts_b)
                        + grp * HW4_ + pix4;
    float4*       dst = reinterpret_cast<float4*>(out_b)
                        + grp * HW4_ + pix4;

    float4 v0 = __ldcs(src);
    float4 v1 = __ldcs(src + CGRP * HW4_);
    float4 v2 = __ldcs(src + 2 * CGRP * HW4_);
    float4 v3 = __ldcs(src + 3 * CGRP * HW4_);

    v0.x *= m.x; v0.y *= m.y; v0.z *= m.z; v0.w *= m.w;
    v1.x *= m.x; v1.y *= m.y; v1.z *= m.z; v1.w *= m.w;
    v2.x *= m.x; v2.y *= m.y; v2.z *= m.z; v2.w *= m.w;
    v3.x *= m.x; v3.y *= m.y; v3.z *= m.z; v3.w *= m.w;

    __stwt(dst,                 v0);
    __stwt(dst + CGRP * HW4_,   v1);
    __stwt(dst + 2 * CGRP * HW4_, v2);
    __stwt(dst + 3 * CGRP * HW4_, v3);
}

// ---------------------------------------------------------------------------
extern "C" void kernel_launch(void* const* d_in, const int* in_sizes, int n_in,
                              void* d_out, int out_size) {
    const float* pts = (const float*)d_in[0];
    float*       out = (float*)d_out;

    float *part_dev, *probs_dev, *mask_dev;
    cudaGetSymbolAddress((void**)&part_dev,  g_part);
    cudaGetSymbolAddress((void**)&probs_dev, g_probs);
    cudaGetSymbolAddress((void**)&mask_dev,  g_mask);

    for (int b = 0; b < B_; ++b) {
        const float* pts_b = pts + (size_t)b * C_ * HW_;
        float*       out_b = out + (size_t)b * C_ * HW_;

        k_probs_part<<<(NCHUNK * HW4_) / 256, 256>>>(pts_b, part_dev);
        k_combine   <<<HW4_ / 256, 256>>>(part_dev, probs_dev);
        k_mask      <<<HW_  / 256, 256>>>(probs_dev, mask_dev);
        k_mul       <<<(CGRP * HW4_) / 256, 256>>>(pts_b, mask_dev, out_b);
    }
}